// round 12
// baseline (speedup 1.0000x reference)
#include <cuda_runtime.h>
#include <cuda_fp16.h>
#include <cstdint>

typedef unsigned long long u64;
typedef uint32_t u32;

__device__ double g_devsum;
__device__ int    g_flagcnt;
__device__ int    g_blkdone;
__device__ u32    g_wmaxb;          // zero-init; monotone atomicMax -> replay-deterministic
__device__ float  g_wnorm[1024];
__device__ int    g_code[65536];
__device__ int    g_flaglist[65536];
// [tile8][chunk4] regions of 16KB: SW128-swizzled [sym128][k64] fp16 (w scaled by 1024)
__device__ __align__(16) unsigned char g_wblob[32 * 16384];
// approximate scores: r = d_app - A, fp16, [pixel][sym] (2KB per pixel)
__device__ __align__(16) unsigned short g_dstore[65536 * 1024];

__device__ __forceinline__ u32 smem_to_u32(const void* p) {
    u32 a;
    asm("{ .reg .u64 t; cvta.to.shared.u64 t, %1; cvt.u32.u64 %0, t; }" : "=r"(a) : "l"(p));
    return a;
}
#define SW128(o) ((o) ^ (((o) >> 3) & 0x70))

#define LDSM4(r0, r1, r2, r3, addr) \
    asm volatile("ldmatrix.sync.aligned.m8n8.x4.shared.b16 {%0,%1,%2,%3}, [%4];" \
                 : "=r"(r0), "=r"(r1), "=r"(r2), "=r"(r3) : "r"(addr))

#define MMA16816(c0, c1, c2, c3, a0, a1, a2, a3, b0, b1) \
    asm volatile("mma.sync.aligned.m16n8k16.row.col.f32.f16.f16.f32 " \
                 "{%0,%1,%2,%3},{%4,%5,%6,%7},{%8,%9},{%0,%1,%2,%3};" \
                 : "+f"(c0), "+f"(c1), "+f"(c2), "+f"(c3) \
                 : "r"(a0), "r"(a1), "r"(a2), "r"(a3), "r"(b0), "r"(b1))

#define CP_ASYNC16(dst, src) \
    asm volatile("cp.async.cg.shared.global [%0], [%1], 16;" :: "r"(dst), "l"(src))
#define CP_COMMIT() asm volatile("cp.async.commit_group;")
#define CP_WAIT1()  asm volatile("cp.async.wait_group 1;")
#define CP_WAIT0()  asm volatile("cp.async.wait_group 0;")

// ================= prep: wnorm + wmax + fp16 W blob (scaled 1024, SW128) ============
__global__ void prep_kernel(const float* __restrict__ W) {
    int s = blockIdx.x, tid = threadIdx.x;
    __shared__ float red[8], redm[8];
    float v = W[s * 256 + tid];
    float acc = v * v;
    float am = fabsf(v);
    #pragma unroll
    for (int o = 16; o; o >>= 1) {
        acc += __shfl_xor_sync(0xffffffffu, acc, o);
        am = fmaxf(am, __shfl_xor_sync(0xffffffffu, am, o));
    }
    if ((tid & 31) == 0) { red[tid >> 5] = acc; redm[tid >> 5] = am; }
    __syncthreads();
    if (tid == 0) {
        float t = 0.f, m = 0.f;
        #pragma unroll
        for (int i = 0; i < 8; i++) { t += red[i]; m = fmaxf(m, redm[i]); }
        g_wnorm[s] = t;
        atomicMax(&g_wmaxb, __float_as_uint(m));
        if (s == 0) { g_devsum = 0.0; g_flagcnt = 0; g_blkdone = 0; }
    }
    int tile = s >> 7, sym = s & 127, c = tid >> 6, k = tid & 63;
    __half h = __float2half(v * 1024.0f);
    u32 off = SW128((u32)(sym * 128 + k * 2));
    *(__half*)(g_wblob + (size_t)(tile * 4 + c) * 16384 + off) = h;
}

// ================= vq: fp16 HMMA GEMM + margin argmin, 2 CTA/SM =====================
#define SM_A     0          // 128 rows x 512B, chunk^row swizzled = 65536
#define SM_BBUF  65536      // 3 x 16384, SW128 layout (ring)
#define SM_PART  65536      // phase-0 overlay: 128 x 65 floats = 33280
#define SM_AROW  98816      // phase-0 overlay: 128 floats (before copies start)
#define SM_RED   65536      // post-loop overlay: u64[128*16*2] = 32768
#define SM_TOTAL 114688     // exactly 14 x 8KB -> 2 CTAs/SM even with 8KB granularity

extern __shared__ char smem[];

__global__ void __launch_bounds__(256, 2)
vq_kernel(const float* __restrict__ X, int npix)
{
    const int tid = threadIdx.x, lane = tid & 31, wid = tid >> 5;
    const int warp_m = wid & 1, warp_n = wid >> 1;
    const int p0 = blockIdx.x * 128;
    const u32 sb = smem_to_u32(smem);

    // ---- phase 0: X -> fp16 A smem (swizzled) + x^2 quad partials ----
    float* part = (float*)(smem + SM_PART);
    const float4* Xg4 = (const float4*)X;
    #pragma unroll 4
    for (int i = 0; i < 32; i++) {
        int q = i * 256 + tid, row = q >> 6, kq = q & 63;
        float4 v = make_float4(0.f, 0.f, 0.f, 0.f);
        if (p0 + row < npix) v = Xg4[(size_t)(p0 + row) * 64 + kq];
        __half h0 = __float2half(v.x), h1 = __float2half(v.y);
        __half h2 = __float2half(v.z), h3 = __float2half(v.w);
        u32 hx = (u32)__half_as_ushort(h0) | ((u32)__half_as_ushort(h1) << 16);
        u32 hy = (u32)__half_as_ushort(h2) | ((u32)__half_as_ushort(h3) << 16);
        u32 aoff = (u32)(row * 512 + ((((kq >> 1) ^ (row & 7))) << 4) + (kq & 1) * 8);
        *(uint2*)(smem + SM_A + aoff) = make_uint2(hx, hy);
        part[row * 65 + kq] = ((v.x * v.x + v.y * v.y) + v.z * v.z) + v.w * v.w;
    }
    __syncthreads();
    float* arow = (float*)(smem + SM_AROW);
    if (tid < 128) {
        float a = 0.f;
        #pragma unroll
        for (int kq = 0; kq < 64; kq++) a += part[tid * 65 + kq];
        arow[tid] = a;
    }
    __syncthreads();
    float a_r[4][2];
    #pragma unroll
    for (int g = 0; g < 4; g++)
        #pragma unroll
        for (int h = 0; h < 2; h++)
            a_r[g][h] = arow[warp_m * 64 + g * 16 + (lane >> 2) + h * 8];
    __syncthreads();

    // ---- async B ring (blob pre-swizzled -> identity copy), 3 stages ----
    auto issue_copy = [&](int g, int buf) {
        #pragma unroll
        for (int j = 0; j < 4; j++) {
            int idx = j * 256 + tid;
            u32 dst = sb + SM_BBUF + (u32)(buf * 16384 + idx * 16);
            const char* src = (const char*)g_wblob + (size_t)g * 16384 + (size_t)idx * 16;
            CP_ASYNC16(dst, src);
        }
        CP_COMMIT();
    };
    issue_copy(0, 0);
    issue_copy(1, 1);

    float acc[4][4][4];
    #pragma unroll
    for (int g = 0; g < 4; g++)
        #pragma unroll
        for (int n = 0; n < 4; n++)
            #pragma unroll
            for (int j = 0; j < 4; j++) acc[g][n][j] = 0.f;
    u64 m1[4][2], m2[4][2];
    #pragma unroll
    for (int g = 0; g < 4; g++) { m1[g][0] = m1[g][1] = ~0ull; m2[g][0] = m2[g][1] = ~0ull; }

    u32 arb[4], arx[4];
    #pragma unroll
    for (int gi = 0; gi < 4; gi++) {
        int r = warp_m * 64 + gi * 16 + (lane & 15);
        arb[gi] = sb + SM_A + (u32)(r * 512);
        arx[gi] = (u32)(r & 7);
    }
    const u32 as16 = (u32)(lane >> 4);
    u32 brb[2], brx[2];
    #pragma unroll
    for (int n2 = 0; n2 < 2; n2++) {
        int sym = warp_n * 32 + n2 * 16 + (lane & 7) + (lane >> 4) * 8;
        brb[n2] = sb + SM_BBUF + (u32)(sym * 128);
        brx[n2] = (u32)(sym & 7);
    }
    const u32 bs0 = (u32)((lane >> 3) & 1);

    int buf = 0;            // = g % 3
    for (int g = 0; g < 32; g++) {
        const int tile = g >> 2, c = g & 3;
        if (g == 31) { CP_WAIT0(); } else { CP_WAIT1(); }
        __syncthreads();    // my group-g data + everyone's; reads of g-1 all done
        if (g + 2 < 32) {
            int nbuf = buf + 2; if (nbuf >= 3) nbuf -= 3;   // (g+2)%3 == (g-1)%3's slot
            issue_copy(g + 2, nbuf);
        }
        #pragma unroll
        for (int ks = 0; ks < 4; ks++) {
            u32 af[4][4], bfr[2][4];
            const u32 ch = (u32)(c * 8 + ks * 2) + as16;
            #pragma unroll
            for (int gi = 0; gi < 4; gi++)
                LDSM4(af[gi][0], af[gi][1], af[gi][2], af[gi][3],
                      arb[gi] + ((ch ^ arx[gi]) << 4));
            const u32 bseg = (u32)(ks * 2) + bs0;
            #pragma unroll
            for (int n2 = 0; n2 < 2; n2++)
                LDSM4(bfr[n2][0], bfr[n2][1], bfr[n2][2], bfr[n2][3],
                      brb[n2] + (u32)(buf * 16384) + ((bseg ^ brx[n2]) << 4));
            #pragma unroll
            for (int gi = 0; gi < 4; gi++)
                #pragma unroll
                for (int nf = 0; nf < 4; nf++)
                    MMA16816(acc[gi][nf][0], acc[gi][nf][1], acc[gi][nf][2], acc[gi][nf][3],
                             af[gi][0], af[gi][1], af[gi][2], af[gi][3],
                             bfr[nf >> 1][(nf & 1) * 2], bfr[nf >> 1][(nf & 1) * 2 + 1]);
        }
        if (c == 3) {
            // d = fl(fl(A+B) - 2*(acc/1024)) ; -2^-9 exact in fma.  Also store r = d - A.
            const int tbase = tile * 128 + warp_n * 32;
            #pragma unroll
            for (int nf = 0; nf < 4; nf++) {
                const int sym0 = tbase + nf * 8 + (lane & 3) * 2;
                const float w0 = g_wnorm[sym0];
                const float w1 = g_wnorm[sym0 + 1];
                #pragma unroll
                for (int gi = 0; gi < 4; gi++) {
                    #pragma unroll
                    for (int h = 0; h < 2; h++) {
                        const int row = warp_m * 64 + gi * 16 + (lane >> 2) + h * 8;
                        float d0 = __fmaf_rn(-0.001953125f, acc[gi][nf][h * 2],
                                             __fadd_rn(a_r[gi][h], w0));
                        float d1 = __fmaf_rn(-0.001953125f, acc[gi][nf][h * 2 + 1],
                                             __fadd_rn(a_r[gi][h], w1));
                        if (p0 + row < npix) {
                            __half2 rp = __floats2half2_rn(__fsub_rn(d0, a_r[gi][h]),
                                                           __fsub_rn(d1, a_r[gi][h]));
                            *(u32*)(g_dstore + (size_t)(p0 + row) * 1024 + sym0) =
                                *(u32*)&rp;
                        }
                        u64 k0 = ((u64)__float_as_uint(d0) << 32) | (u32)sym0;
                        u64 k1 = ((u64)__float_as_uint(d1) << 32) | (u32)(sym0 + 1);
                        if (k0 < m1[gi][h]) { m2[gi][h] = m1[gi][h]; m1[gi][h] = k0; }
                        else if (k0 < m2[gi][h]) m2[gi][h] = k0;
                        if (k1 < m1[gi][h]) { m2[gi][h] = m1[gi][h]; m1[gi][h] = k1; }
                        else if (k1 < m2[gi][h]) m2[gi][h] = k1;
                        acc[gi][nf][h * 2] = 0.f;
                        acc[gi][nf][h * 2 + 1] = 0.f;
                    }
                }
            }
        }
        if (++buf == 3) buf = 0;
    }
    __syncthreads();   // B ring dead; RED overlay becomes live

    // ---- top-2 merge + per-pixel certified margin ----
    u64* red2 = (u64*)(smem + SM_RED);
    const int slot = warp_n * 4 + (lane & 3);
    #pragma unroll
    for (int gi = 0; gi < 4; gi++)
        #pragma unroll
        for (int h = 0; h < 2; h++) {
            int row = warp_m * 64 + gi * 16 + (lane >> 2) + h * 8;
            red2[(row * 16 + slot) * 2]     = m1[gi][h];
            red2[(row * 16 + slot) * 2 + 1] = m2[gi][h];
        }
    __syncthreads();
    if (tid < 128) {
        u64 b1 = ~0ull, b2 = ~0ull;
        #pragma unroll
        for (int t = 0; t < 16; t++) {
            u64 x1 = red2[(tid * 16 + t) * 2];
            u64 x2 = red2[(tid * 16 + t) * 2 + 1];
            if (x1 < b1) { u64 c2 = (b1 < x2) ? b1 : x2; b1 = x1; b2 = (c2 < b2) ? c2 : b2; }
            else if (x1 < b2) b2 = x1;
        }
        // |x| sum from fp16 A tile (bound input only; constant covers fp16 quant)
        float sab = 0.f;
        const u32 rx7 = (u32)(tid & 7);
        #pragma unroll 8
        for (u32 ch = 0; ch < 32; ch++) {
            uint4 v = *(const uint4*)(smem + SM_A + tid * 512 + ((ch ^ rx7) << 4));
            const u32 wd[4] = {v.x, v.y, v.z, v.w};
            #pragma unroll
            for (int t = 0; t < 4; t++) {
                float2 f = __half22float2(*(const __half2*)&wd[t]);
                sab += fabsf(f.x) + fabsf(f.y);
            }
        }
        if (p0 + tid < npix) {
            g_code[p0 + tid] = (int)(u32)b1;
            float d1 = __uint_as_float((u32)(b1 >> 32));
            float d2 = __uint_as_float((u32)(b2 >> 32));
            float wmax = __uint_as_float(g_wmaxb);
            float marg = sab * wmax * 0.00398f + 1.0e-4f;
            if (!(d2 - d1 > marg)) {
                int fs = atomicAdd(&g_flagcnt, 1);
                g_flaglist[fs] = p0 + tid;
            }
        }
    }
}

// ================= candfix: exact rescore of CANDIDATES only ========================
__device__ __forceinline__ u64 chain_key(const float* xr, const float* __restrict__ W,
                                         int sym, float A) {
    const float4* wp = (const float4*)(W + (size_t)sym * 256);
    float acc = 0.f;
    #pragma unroll 8
    for (int k = 0; k < 64; k++) {
        float4 w4 = __ldg(&wp[k]);
        float4 x4 = *(const float4*)(xr + k * 4);
        acc = __fmaf_rn(x4.x, w4.x, acc);
        acc = __fmaf_rn(x4.y, w4.y, acc);
        acc = __fmaf_rn(x4.z, w4.z, acc);
        acc = __fmaf_rn(x4.w, w4.w, acc);
    }
    float d = __fmaf_rn(-2.f, acc, __fadd_rn(A, g_wnorm[sym]));
    return ((u64)__float_as_uint(d) << 32) | (u32)sym;
}

__global__ void __launch_bounds__(256, 1)
candfix_kernel(const float* __restrict__ X, const float* __restrict__ W)
{
    __shared__ float xrow[8][256];
    __shared__ float pp[8][64];
    __shared__ int   clist[8][34];
    __shared__ int   scnt[8];
    __shared__ float sA[8];
    const int lane = threadIdx.x & 31, w = threadIdx.x >> 5;
    const int wg = blockIdx.x * 8 + w, nw = gridDim.x * 8;
    const int cnt = g_flagcnt;
    const float wmax = __uint_as_float(g_wmaxb);

    for (int i = wg; i < cnt; i += nw) {
        const int pixel = g_flaglist[i];
        float sabs_l = 0.f;
        #pragma unroll
        for (int j = 0; j < 2; j++) {
            int kq = lane + j * 32;
            float4 v = ((const float4*)X)[(size_t)pixel * 64 + kq];
            *(float4*)&xrow[w][kq * 4] = v;
            pp[w][kq] = ((v.x * v.x + v.y * v.y) + v.z * v.z) + v.w * v.w;
            sabs_l += ((fabsf(v.x) + fabsf(v.y)) + fabsf(v.z)) + fabsf(v.w);
        }
        if (lane == 0) scnt[w] = 0;
        __syncwarp();
        if (lane == 0) {
            float a = 0.f;
            #pragma unroll
            for (int k = 0; k < 64; k++) a += pp[w][k];
            sA[w] = a;
        }
        #pragma unroll
        for (int o = 16; o; o >>= 1) sabs_l += __shfl_xor_sync(0xffffffffu, sabs_l, o);
        __syncwarp();
        const float A = sA[w];

        const uint4* rrow = (const uint4*)(g_dstore + (size_t)pixel * 1024);
        uint4 rv[4];
        float rmin = 3.4e38f;
        #pragma unroll
        for (int j = 0; j < 4; j++) {
            rv[j] = rrow[lane * 4 + j];
            const u32 wd[4] = {rv[j].x, rv[j].y, rv[j].z, rv[j].w};
            #pragma unroll
            for (int t = 0; t < 4; t++) {
                float2 f = __half22float2(*(const __half2*)&wd[t]);
                rmin = fminf(rmin, fminf(f.x, f.y));
            }
        }
        #pragma unroll
        for (int o = 16; o; o >>= 1)
            rmin = fminf(rmin, __shfl_xor_sync(0xffffffffu, rmin, o));
        const float thr = rmin + sabs_l * wmax * 0.004f + 6.5e-4f;

        #pragma unroll
        for (int j = 0; j < 4; j++) {
            const u32 wd[4] = {rv[j].x, rv[j].y, rv[j].z, rv[j].w};
            #pragma unroll
            for (int t = 0; t < 4; t++) {
                float2 f = __half22float2(*(const __half2*)&wd[t]);
                int sym = (lane * 16 + j * 4 + t) * 2;
                if (f.x <= thr) {
                    int pos = atomicAdd(&scnt[w], 1);
                    if (pos < 33) clist[w][pos] = sym;
                }
                if (f.y <= thr) {
                    int pos = atomicAdd(&scnt[w], 1);
                    if (pos < 33) clist[w][pos] = sym + 1;
                }
            }
        }
        __syncwarp();
        const int n = scnt[w];
        u64 key = ~0ull;
        if (n <= 32) {
            if (lane < n) key = chain_key(xrow[w], W, clist[w][lane], A);
        } else {
            for (int sym = lane; sym < 1024; sym += 32) {
                u64 k2 = chain_key(xrow[w], W, sym, A);
                if (k2 < key) key = k2;
            }
        }
        #pragma unroll
        for (int o = 16; o; o >>= 1) {
            u64 other = __shfl_xor_sync(0xffffffffu, key, o);
            if (other < key) key = other;
        }
        if (lane == 0) g_code[pixel] = (int)(u32)key;
        __syncwarp();
    }
}

// ================= gather + deviation + tail (last block) ===========================
__global__ void gather_kernel(const float* __restrict__ X, const float* __restrict__ W,
                              float* __restrict__ out, int npix, long long out_cap)
{
    __shared__ float psum[256];
    __shared__ int codes[128];
    __shared__ int lastflag;
    const int tid = threadIdx.x;
    const int p0 = blockIdx.x * 128;
    if (tid < 128) codes[tid] = (p0 + tid < npix) ? g_code[p0 + tid] : 0;
    __syncthreads();
    const float4* Xg4 = (const float4*)X;
    const float4* Wg4 = (const float4*)W;
    float4* out4 = (float4*)out;
    float dsum = 0.f;
    #pragma unroll 4
    for (int i = 0; i < 32; i++) {
        int q = i * 256 + tid, row = q >> 6, kq = q & 63;
        long long gp = p0 + row;
        if (gp < npix) {
            int c = codes[row];
            float4 wv = Wg4[(size_t)c * 64 + kq];
            float4 xv = Xg4[gp * 64 + kq];
            float t0 = wv.x - xv.x, t1 = wv.y - xv.y;
            float t2 = wv.z - xv.z, t3 = wv.w - xv.w;
            float4 ov;
            ov.x = xv.x + t0; ov.y = xv.y + t1; ov.z = xv.z + t2; ov.w = xv.w + t3;
            long long e = gp * 64 + kq;
            if (e * 4 + 3 < out_cap) out4[e] = ov;
            dsum += t0 * t0 + t1 * t1 + t2 * t2 + t3 * t3;
        }
    }
    psum[tid] = dsum;
    __syncthreads();
    #pragma unroll
    for (int sft = 128; sft > 0; sft >>= 1) {
        if (tid < sft) psum[tid] += psum[tid + sft];
        __syncthreads();
    }
    if (tid == 0) {
        atomicAdd(&g_devsum, (double)psum[0]);
        __threadfence();
        int done = atomicAdd(&g_blkdone, 1);
        lastflag = (done == (int)gridDim.x - 1);
    }
    __syncthreads();
    if (lastflag) {
        // all blocks' devsum contributions are visible (fence-before-counter)
        double dev = 1.25 * (*(volatile double*)&g_devsum) / (double)((long long)npix * 256);
        long long n = (long long)npix * 256;
        for (long long i = n + tid; i < out_cap; i += blockDim.x)
            out[i] = (float)dev;
    }
}

// ================= launch ===========================================================
extern "C" void kernel_launch(void* const* d_in, const int* in_sizes, int n_in,
                              void* d_out, int out_size) {
    const float* X = (const float*)d_in[0];
    const float* W = (const float*)d_in[1];
    float* out = (float*)d_out;
    const int npix = in_sizes[0] / 256;
    const int S = in_sizes[1] / 256;

    cudaFuncSetAttribute(vq_kernel, cudaFuncAttributeMaxDynamicSharedMemorySize, SM_TOTAL);

    prep_kernel<<<S, 256>>>(W);
    vq_kernel<<<(npix + 127) / 128, 256, SM_TOTAL>>>(X, npix);
    candfix_kernel<<<296, 256>>>(X, W);
    gather_kernel<<<(npix + 127) / 128, 256>>>(X, W, out, npix, (long long)out_size);
}

// round 13
// speedup vs baseline: 1.1840x; 1.1840x over previous
#include <cuda_runtime.h>
#include <cuda_fp16.h>
#include <cstdint>

typedef unsigned long long u64;
typedef uint32_t u32;

__device__ double g_devsum;
__device__ int    g_flagcnt;
__device__ int    g_blkdone;
__device__ u32    g_wmaxb;          // zero-init; monotone atomicMax -> replay-deterministic
__device__ float  g_wnorm[1024];
__device__ int    g_code[65536];
__device__ int    g_flaglist[65536];
// [tile8][chunk4] regions of 16KB: SW128-swizzled [sym128][k64] fp16 (w scaled by 1024)
__device__ __align__(16) unsigned char g_wblob[32 * 16384];
// approximate scores: r = d_app - A, fp16, [pixel][sym] (2KB per pixel)
__device__ __align__(16) unsigned short g_dstore[65536 * 1024];

__device__ __forceinline__ u32 smem_to_u32(const void* p) {
    u32 a;
    asm("{ .reg .u64 t; cvta.to.shared.u64 t, %1; cvt.u32.u64 %0, t; }" : "=r"(a) : "l"(p));
    return a;
}
#define SW128(o) ((o) ^ (((o) >> 3) & 0x70))

#define LDSM4(r0, r1, r2, r3, addr) \
    asm volatile("ldmatrix.sync.aligned.m8n8.x4.shared.b16 {%0,%1,%2,%3}, [%4];" \
                 : "=r"(r0), "=r"(r1), "=r"(r2), "=r"(r3) : "r"(addr))

#define MMA16816(c0, c1, c2, c3, a0, a1, a2, a3, b0, b1) \
    asm volatile("mma.sync.aligned.m16n8k16.row.col.f32.f16.f16.f32 " \
                 "{%0,%1,%2,%3},{%4,%5,%6,%7},{%8,%9},{%0,%1,%2,%3};" \
                 : "+f"(c0), "+f"(c1), "+f"(c2), "+f"(c3) \
                 : "r"(a0), "r"(a1), "r"(a2), "r"(a3), "r"(b0), "r"(b1))

#define CP_ASYNC16(dst, src) \
    asm volatile("cp.async.cg.shared.global [%0], [%1], 16;" :: "r"(dst), "l"(src))
#define CP_COMMIT() asm volatile("cp.async.commit_group;")
#define CP_WAIT1()  asm volatile("cp.async.wait_group 1;")
#define CP_WAIT0()  asm volatile("cp.async.wait_group 0;")

// ================= prep: wnorm + wmax + fp16 W blob (scaled 1024, SW128) ============
__global__ void prep_kernel(const float* __restrict__ W) {
    int s = blockIdx.x, tid = threadIdx.x;
    __shared__ float red[8], redm[8];
    float v = W[s * 256 + tid];
    float acc = v * v;
    float am = fabsf(v);
    #pragma unroll
    for (int o = 16; o; o >>= 1) {
        acc += __shfl_xor_sync(0xffffffffu, acc, o);
        am = fmaxf(am, __shfl_xor_sync(0xffffffffu, am, o));
    }
    if ((tid & 31) == 0) { red[tid >> 5] = acc; redm[tid >> 5] = am; }
    __syncthreads();
    if (tid == 0) {
        float t = 0.f, m = 0.f;
        #pragma unroll
        for (int i = 0; i < 8; i++) { t += red[i]; m = fmaxf(m, redm[i]); }
        g_wnorm[s] = t;
        atomicMax(&g_wmaxb, __float_as_uint(m));
        if (s == 0) { g_devsum = 0.0; g_flagcnt = 0; g_blkdone = 0; }
    }
    int tile = s >> 7, sym = s & 127, c = tid >> 6, k = tid & 63;
    __half h = __float2half(v * 1024.0f);
    u32 off = SW128((u32)(sym * 128 + k * 2));
    *(__half*)(g_wblob + (size_t)(tile * 4 + c) * 16384 + off) = h;
}

// ================= vq: fp16 HMMA GEMM, M=64 tiles, 3 CTAs/SM ========================
#define SM_A     0          // 64 rows x 512B, chunk^row swizzled = 32768
#define SM_BBUF  32768      // 2 x 16384, SW128 layout
#define SM_PART  32768      // phase-0 overlay: 64 x 65 floats = 16640 (B dead then)
#define SM_RED   32768      // post-loop overlay: u64[64*16] = 8192
#define SM_REDF  40960      // post-loop overlay: float[64*16] = 4096
#define SM_AROW  65536      // 64 floats
#define SM_TOTAL 65792

extern __shared__ char smem[];

__global__ void __launch_bounds__(256, 3)
vq_kernel(const float* __restrict__ X, int npix)
{
    const int tid = threadIdx.x, lane = tid & 31, wid = tid >> 5;
    const int warp_m = wid & 1, warp_n = wid >> 1;
    const int p0 = blockIdx.x * 64;
    const u32 sb = smem_to_u32(smem);

    // ---- phase 0: X -> fp16 A smem (swizzled) + x^2 quad partials ----
    float* part = (float*)(smem + SM_PART);
    const float4* Xg4 = (const float4*)X;
    #pragma unroll 4
    for (int i = 0; i < 16; i++) {
        int q = i * 256 + tid, row = q >> 6, kq = q & 63;
        float4 v = make_float4(0.f, 0.f, 0.f, 0.f);
        if (p0 + row < npix) v = Xg4[(size_t)(p0 + row) * 64 + kq];
        __half h0 = __float2half(v.x), h1 = __float2half(v.y);
        __half h2 = __float2half(v.z), h3 = __float2half(v.w);
        u32 hx = (u32)__half_as_ushort(h0) | ((u32)__half_as_ushort(h1) << 16);
        u32 hy = (u32)__half_as_ushort(h2) | ((u32)__half_as_ushort(h3) << 16);
        u32 aoff = (u32)(row * 512 + ((((kq >> 1) ^ (row & 7))) << 4) + (kq & 1) * 8);
        *(uint2*)(smem + SM_A + aoff) = make_uint2(hx, hy);
        part[row * 65 + kq] = ((v.x * v.x + v.y * v.y) + v.z * v.z) + v.w * v.w;
    }
    __syncthreads();
    float* arow = (float*)(smem + SM_AROW);
    if (tid < 64) {
        float a = 0.f;
        #pragma unroll
        for (int kq = 0; kq < 64; kq++) a += part[tid * 65 + kq];
        arow[tid] = a;
    }
    __syncthreads();
    float a_r[2][2];
    #pragma unroll
    for (int g = 0; g < 2; g++)
        #pragma unroll
        for (int h = 0; h < 2; h++)
            a_r[g][h] = arow[warp_m * 32 + g * 16 + (lane >> 2) + h * 8];
    __syncthreads();

    // ---- async B double buffer (blob pre-swizzled -> identity copy) ----
    auto issue_copy = [&](int g, int buf) {
        #pragma unroll
        for (int j = 0; j < 4; j++) {
            int idx = j * 256 + tid;
            u32 dst = sb + SM_BBUF + (u32)(buf * 16384 + idx * 16);
            const char* src = (const char*)g_wblob + (size_t)g * 16384 + (size_t)idx * 16;
            CP_ASYNC16(dst, src);
        }
        CP_COMMIT();
    };
    issue_copy(0, 0);
    issue_copy(1, 1);

    float acc[2][4][4];
    #pragma unroll
    for (int g = 0; g < 2; g++)
        #pragma unroll
        for (int n = 0; n < 4; n++)
            #pragma unroll
            for (int j = 0; j < 4; j++) acc[g][n][j] = 0.f;
    u64   m1[2][2];
    float m2f[2][2];
    #pragma unroll
    for (int g = 0; g < 2; g++) {
        m1[g][0] = m1[g][1] = ~0ull;
        m2f[g][0] = m2f[g][1] = 3.4e38f;
    }

    u32 arb[2], arx[2];
    #pragma unroll
    for (int gi = 0; gi < 2; gi++) {
        int r = warp_m * 32 + gi * 16 + (lane & 15);
        arb[gi] = sb + SM_A + (u32)(r * 512);
        arx[gi] = (u32)(r & 7);
    }
    const u32 as16 = (u32)(lane >> 4);
    u32 brb[2], brx[2];
    #pragma unroll
    for (int n2 = 0; n2 < 2; n2++) {
        int sym = warp_n * 32 + n2 * 16 + (lane & 7) + (lane >> 4) * 8;
        brb[n2] = sb + SM_BBUF + (u32)(sym * 128);
        brx[n2] = (u32)(sym & 7);
    }
    const u32 bs0 = (u32)((lane >> 3) & 1);

    for (int g = 0; g < 32; g++) {
        const int tile = g >> 2, c = g & 3, buf = g & 1;
        if (g == 31) { CP_WAIT0(); } else { CP_WAIT1(); }
        __syncthreads();
        #pragma unroll
        for (int ks = 0; ks < 4; ks++) {
            u32 af[2][4], bfr[2][4];
            const u32 ch = (u32)(c * 8 + ks * 2) + as16;
            #pragma unroll
            for (int gi = 0; gi < 2; gi++)
                LDSM4(af[gi][0], af[gi][1], af[gi][2], af[gi][3],
                      arb[gi] + ((ch ^ arx[gi]) << 4));
            const u32 bseg = (u32)(ks * 2) + bs0;
            #pragma unroll
            for (int n2 = 0; n2 < 2; n2++)
                LDSM4(bfr[n2][0], bfr[n2][1], bfr[n2][2], bfr[n2][3],
                      brb[n2] + (u32)(buf * 16384) + ((bseg ^ brx[n2]) << 4));
            #pragma unroll
            for (int gi = 0; gi < 2; gi++)
                #pragma unroll
                for (int nf = 0; nf < 4; nf++)
                    MMA16816(acc[gi][nf][0], acc[gi][nf][1], acc[gi][nf][2], acc[gi][nf][3],
                             af[gi][0], af[gi][1], af[gi][2], af[gi][3],
                             bfr[nf >> 1][(nf & 1) * 2], bfr[nf >> 1][(nf & 1) * 2 + 1]);
        }
        if (c == 3) {
            // d = fl(fl(A+B) - 2*(acc/1024)) ; -2^-9 exact in fma.  Also store r = d - A.
            const int tbase = tile * 128 + warp_n * 32;
            #pragma unroll
            for (int nf = 0; nf < 4; nf++) {
                const int sym0 = tbase + nf * 8 + (lane & 3) * 2;
                const float w0 = g_wnorm[sym0];
                const float w1 = g_wnorm[sym0 + 1];
                #pragma unroll
                for (int gi = 0; gi < 2; gi++) {
                    #pragma unroll
                    for (int h = 0; h < 2; h++) {
                        const int row = warp_m * 32 + gi * 16 + (lane >> 2) + h * 8;
                        float d0 = __fmaf_rn(-0.001953125f, acc[gi][nf][h * 2],
                                             __fadd_rn(a_r[gi][h], w0));
                        float d1 = __fmaf_rn(-0.001953125f, acc[gi][nf][h * 2 + 1],
                                             __fadd_rn(a_r[gi][h], w1));
                        if (p0 + row < npix) {
                            __half2 rp = __floats2half2_rn(__fsub_rn(d0, a_r[gi][h]),
                                                           __fsub_rn(d1, a_r[gi][h]));
                            *(u32*)(g_dstore + (size_t)(p0 + row) * 1024 + sym0) =
                                *(u32*)&rp;
                        }
                        u64 k0 = ((u64)__float_as_uint(d0) << 32) | (u32)sym0;
                        u64 k1 = ((u64)__float_as_uint(d1) << 32) | (u32)(sym0 + 1);
                        // fminf drops the NaN from the ~0ull sentinel
                        if (k0 < m1[gi][h]) {
                            m2f[gi][h] = fminf(m2f[gi][h],
                                               __uint_as_float((u32)(m1[gi][h] >> 32)));
                            m1[gi][h] = k0;
                        } else m2f[gi][h] = fminf(m2f[gi][h], d0);
                        if (k1 < m1[gi][h]) {
                            m2f[gi][h] = fminf(m2f[gi][h],
                                               __uint_as_float((u32)(m1[gi][h] >> 32)));
                            m1[gi][h] = k1;
                        } else m2f[gi][h] = fminf(m2f[gi][h], d1);
                        acc[gi][nf][h * 2] = 0.f;
                        acc[gi][nf][h * 2 + 1] = 0.f;
                    }
                }
            }
        }
        __syncthreads();
        if (g + 2 < 32) issue_copy(g + 2, buf);
    }
    __syncthreads();   // B buffers dead; RED overlay becomes live

    // ---- top-2 merge + per-pixel certified margin ----
    u64*   red2 = (u64*)(smem + SM_RED);
    float* redf = (float*)(smem + SM_REDF);
    const int slot = warp_n * 4 + (lane & 3);
    #pragma unroll
    for (int gi = 0; gi < 2; gi++)
        #pragma unroll
        for (int h = 0; h < 2; h++) {
            int row = warp_m * 32 + gi * 16 + (lane >> 2) + h * 8;
            red2[row * 16 + slot] = m1[gi][h];
            redf[row * 16 + slot] = m2f[gi][h];
        }
    __syncthreads();
    if (tid < 64) {
        u64 b1 = ~0ull;
        float b2 = 3.4e38f;
        #pragma unroll
        for (int t = 0; t < 16; t++) {
            u64 k1 = red2[tid * 16 + t];
            float f2 = redf[tid * 16 + t];
            if (k1 < b1) {
                b2 = fminf(b2, __uint_as_float((u32)(b1 >> 32)));
                b1 = k1;
            } else {
                b2 = fminf(b2, __uint_as_float((u32)(k1 >> 32)));
            }
            b2 = fminf(b2, f2);
        }
        // |x| sum from fp16 A tile (bound input only; constant covers fp16 quant)
        float sab = 0.f;
        const u32 rx7 = (u32)(tid & 7);
        #pragma unroll 8
        for (u32 ch = 0; ch < 32; ch++) {
            uint4 v = *(const uint4*)(smem + SM_A + tid * 512 + ((ch ^ rx7) << 4));
            const u32 wd[4] = {v.x, v.y, v.z, v.w};
            #pragma unroll
            for (int t = 0; t < 4; t++) {
                float2 f = __half22float2(*(const __half2*)&wd[t]);
                sab += fabsf(f.x) + fabsf(f.y);
            }
        }
        if (p0 + tid < npix) {
            g_code[p0 + tid] = (int)(u32)b1;
            float d1 = __uint_as_float((u32)(b1 >> 32));
            float wmax = __uint_as_float(g_wmaxb);
            float marg = sab * wmax * 0.00398f + 1.0e-4f;
            if (!(b2 - d1 > marg)) {
                int fs = atomicAdd(&g_flagcnt, 1);
                g_flaglist[fs] = p0 + tid;
            }
        }
    }
}

// ================= candfix: exact rescore of CANDIDATES only ========================
__device__ __forceinline__ u64 chain_key(const float* xr, const float* __restrict__ W,
                                         int sym, float A) {
    const float4* wp = (const float4*)(W + (size_t)sym * 256);
    float acc = 0.f;
    #pragma unroll 8
    for (int k = 0; k < 64; k++) {
        float4 w4 = __ldg(&wp[k]);
        float4 x4 = *(const float4*)(xr + k * 4);
        acc = __fmaf_rn(x4.x, w4.x, acc);
        acc = __fmaf_rn(x4.y, w4.y, acc);
        acc = __fmaf_rn(x4.z, w4.z, acc);
        acc = __fmaf_rn(x4.w, w4.w, acc);
    }
    float d = __fmaf_rn(-2.f, acc, __fadd_rn(A, g_wnorm[sym]));
    return ((u64)__float_as_uint(d) << 32) | (u32)sym;
}

__global__ void __launch_bounds__(256, 1)
candfix_kernel(const float* __restrict__ X, const float* __restrict__ W)
{
    __shared__ float xrow[8][256];
    __shared__ float pp[8][64];
    __shared__ int   clist[8][34];
    __shared__ int   scnt[8];
    __shared__ float sA[8];
    const int lane = threadIdx.x & 31, w = threadIdx.x >> 5;
    const int wg = blockIdx.x * 8 + w, nw = gridDim.x * 8;
    const int cnt = g_flagcnt;
    const float wmax = __uint_as_float(g_wmaxb);

    for (int i = wg; i < cnt; i += nw) {
        const int pixel = g_flaglist[i];
        float sabs_l = 0.f;
        #pragma unroll
        for (int j = 0; j < 2; j++) {
            int kq = lane + j * 32;
            float4 v = ((const float4*)X)[(size_t)pixel * 64 + kq];
            *(float4*)&xrow[w][kq * 4] = v;
            pp[w][kq] = ((v.x * v.x + v.y * v.y) + v.z * v.z) + v.w * v.w;
            sabs_l += ((fabsf(v.x) + fabsf(v.y)) + fabsf(v.z)) + fabsf(v.w);
        }
        if (lane == 0) scnt[w] = 0;
        __syncwarp();
        if (lane == 0) {
            float a = 0.f;
            #pragma unroll
            for (int k = 0; k < 64; k++) a += pp[w][k];
            sA[w] = a;
        }
        #pragma unroll
        for (int o = 16; o; o >>= 1) sabs_l += __shfl_xor_sync(0xffffffffu, sabs_l, o);
        __syncwarp();
        const float A = sA[w];

        const uint4* rrow = (const uint4*)(g_dstore + (size_t)pixel * 1024);
        uint4 rv[4];
        float rmin = 3.4e38f;
        #pragma unroll
        for (int j = 0; j < 4; j++) {
            rv[j] = rrow[lane * 4 + j];
            const u32 wd[4] = {rv[j].x, rv[j].y, rv[j].z, rv[j].w};
            #pragma unroll
            for (int t = 0; t < 4; t++) {
                float2 f = __half22float2(*(const __half2*)&wd[t]);
                rmin = fminf(rmin, fminf(f.x, f.y));
            }
        }
        #pragma unroll
        for (int o = 16; o; o >>= 1)
            rmin = fminf(rmin, __shfl_xor_sync(0xffffffffu, rmin, o));
        const float thr = rmin + sabs_l * wmax * 0.004f + 6.5e-4f;

        #pragma unroll
        for (int j = 0; j < 4; j++) {
            const u32 wd[4] = {rv[j].x, rv[j].y, rv[j].z, rv[j].w};
            #pragma unroll
            for (int t = 0; t < 4; t++) {
                float2 f = __half22float2(*(const __half2*)&wd[t]);
                int sym = (lane * 16 + j * 4 + t) * 2;
                if (f.x <= thr) {
                    int pos = atomicAdd(&scnt[w], 1);
                    if (pos < 33) clist[w][pos] = sym;
                }
                if (f.y <= thr) {
                    int pos = atomicAdd(&scnt[w], 1);
                    if (pos < 33) clist[w][pos] = sym + 1;
                }
            }
        }
        __syncwarp();
        const int n = scnt[w];
        u64 key = ~0ull;
        if (n <= 32) {
            if (lane < n) key = chain_key(xrow[w], W, clist[w][lane], A);
        } else {
            for (int sym = lane; sym < 1024; sym += 32) {
                u64 k2 = chain_key(xrow[w], W, sym, A);
                if (k2 < key) key = k2;
            }
        }
        #pragma unroll
        for (int o = 16; o; o >>= 1) {
            u64 other = __shfl_xor_sync(0xffffffffu, key, o);
            if (other < key) key = other;
        }
        if (lane == 0) g_code[pixel] = (int)(u32)key;
        __syncwarp();
    }
}

// ================= gather + deviation + tail (last block) ===========================
__global__ void gather_kernel(const float* __restrict__ X, const float* __restrict__ W,
                              float* __restrict__ out, int npix, long long out_cap)
{
    __shared__ float psum[256];
    __shared__ int codes[128];
    __shared__ int lastflag;
    const int tid = threadIdx.x;
    const int p0 = blockIdx.x * 128;
    if (tid < 128) codes[tid] = (p0 + tid < npix) ? g_code[p0 + tid] : 0;
    __syncthreads();
    const float4* Xg4 = (const float4*)X;
    const float4* Wg4 = (const float4*)W;
    float4* out4 = (float4*)out;
    float dsum = 0.f;
    #pragma unroll 4
    for (int i = 0; i < 32; i++) {
        int q = i * 256 + tid, row = q >> 6, kq = q & 63;
        long long gp = p0 + row;
        if (gp < npix) {
            int c = codes[row];
            float4 wv = Wg4[(size_t)c * 64 + kq];
            float4 xv = Xg4[gp * 64 + kq];
            float t0 = wv.x - xv.x, t1 = wv.y - xv.y;
            float t2 = wv.z - xv.z, t3 = wv.w - xv.w;
            float4 ov;
            ov.x = xv.x + t0; ov.y = xv.y + t1; ov.z = xv.z + t2; ov.w = xv.w + t3;
            long long e = gp * 64 + kq;
            if (e * 4 + 3 < out_cap) out4[e] = ov;
            dsum += t0 * t0 + t1 * t1 + t2 * t2 + t3 * t3;
        }
    }
    psum[tid] = dsum;
    __syncthreads();
    #pragma unroll
    for (int sft = 128; sft > 0; sft >>= 1) {
        if (tid < sft) psum[tid] += psum[tid + sft];
        __syncthreads();
    }
    if (tid == 0) {
        atomicAdd(&g_devsum, (double)psum[0]);
        __threadfence();
        int done = atomicAdd(&g_blkdone, 1);
        lastflag = (done == (int)gridDim.x - 1);
    }
    __syncthreads();
    if (lastflag) {
        double dev = 1.25 * (*(volatile double*)&g_devsum) / (double)((long long)npix * 256);
        long long n = (long long)npix * 256;
        for (long long i = n + tid; i < out_cap; i += blockDim.x)
            out[i] = (float)dev;
    }
}

// ================= launch ===========================================================
extern "C" void kernel_launch(void* const* d_in, const int* in_sizes, int n_in,
                              void* d_out, int out_size) {
    const float* X = (const float*)d_in[0];
    const float* W = (const float*)d_in[1];
    float* out = (float*)d_out;
    const int npix = in_sizes[0] / 256;
    const int S = in_sizes[1] / 256;

    cudaFuncSetAttribute(vq_kernel, cudaFuncAttributeMaxDynamicSharedMemorySize, SM_TOTAL);

    prep_kernel<<<S, 256>>>(W);
    vq_kernel<<<(npix + 63) / 64, 256, SM_TOTAL>>>(X, npix);
    candfix_kernel<<<296, 256>>>(X, W);
    gather_kernel<<<(npix + 127) / 128, 256>>>(X, W, out, npix, (long long)out_size);
}

// round 14
// speedup vs baseline: 1.2195x; 1.0300x over previous
#include <cuda_runtime.h>
#include <cuda_fp16.h>
#include <cstdint>

typedef unsigned long long u64;
typedef uint32_t u32;

__device__ double g_devsum;
__device__ int    g_flagcnt;
__device__ int    g_blkdone;
__device__ u32    g_wmaxb;          // zero-init; monotone atomicMax -> replay-deterministic
__device__ float  g_wnorm[1024];
__device__ int    g_code[65536];
__device__ int    g_flaglist[65536];
// [tile8][chunk4] regions of 16KB: SW128-swizzled [sym128][k64] fp16 (w scaled by 1024)
__device__ __align__(16) unsigned char g_wblob[32 * 16384];
// approximate scores: r = d_app - A, fp16, [pixel][sym] (2KB per pixel)
__device__ __align__(16) unsigned short g_dstore[65536 * 1024];

__device__ __forceinline__ u32 smem_to_u32(const void* p) {
    u32 a;
    asm("{ .reg .u64 t; cvta.to.shared.u64 t, %1; cvt.u32.u64 %0, t; }" : "=r"(a) : "l"(p));
    return a;
}
#define SW128(o) ((o) ^ (((o) >> 3) & 0x70))

#define LDSM4(r0, r1, r2, r3, addr) \
    asm volatile("ldmatrix.sync.aligned.m8n8.x4.shared.b16 {%0,%1,%2,%3}, [%4];" \
                 : "=r"(r0), "=r"(r1), "=r"(r2), "=r"(r3) : "r"(addr))

#define MMA16816(c0, c1, c2, c3, a0, a1, a2, a3, b0, b1) \
    asm volatile("mma.sync.aligned.m16n8k16.row.col.f32.f16.f16.f32 " \
                 "{%0,%1,%2,%3},{%4,%5,%6,%7},{%8,%9},{%0,%1,%2,%3};" \
                 : "+f"(c0), "+f"(c1), "+f"(c2), "+f"(c3) \
                 : "r"(a0), "r"(a1), "r"(a2), "r"(a3), "r"(b0), "r"(b1))

#define CP_ASYNC16(dst, src) \
    asm volatile("cp.async.cg.shared.global [%0], [%1], 16;" :: "r"(dst), "l"(src))
#define CP_COMMIT() asm volatile("cp.async.commit_group;")
#define CP_WAIT1()  asm volatile("cp.async.wait_group 1;")
#define CP_WAIT0()  asm volatile("cp.async.wait_group 0;")

// ================= prep: wnorm + wmax + fp16 W blob (scaled 1024, SW128) ============
__global__ void prep_kernel(const float* __restrict__ W) {
    int s = blockIdx.x, tid = threadIdx.x;
    __shared__ float red[8], redm[8];
    float v = W[s * 256 + tid];
    float acc = v * v;
    float am = fabsf(v);
    #pragma unroll
    for (int o = 16; o; o >>= 1) {
        acc += __shfl_xor_sync(0xffffffffu, acc, o);
        am = fmaxf(am, __shfl_xor_sync(0xffffffffu, am, o));
    }
    if ((tid & 31) == 0) { red[tid >> 5] = acc; redm[tid >> 5] = am; }
    __syncthreads();
    if (tid == 0) {
        float t = 0.f, m = 0.f;
        #pragma unroll
        for (int i = 0; i < 8; i++) { t += red[i]; m = fmaxf(m, redm[i]); }
        g_wnorm[s] = t;
        atomicMax(&g_wmaxb, __float_as_uint(m));
        if (s == 0) { g_devsum = 0.0; g_flagcnt = 0; g_blkdone = 0; }
    }
    int tile = s >> 7, sym = s & 127, c = tid >> 6, k = tid & 63;
    __half h = __float2half(v * 1024.0f);
    u32 off = SW128((u32)(sym * 128 + k * 2));
    *(__half*)(g_wblob + (size_t)(tile * 4 + c) * 16384 + off) = h;
}

// ================= vq: fp16 HMMA GEMM, M=64 tiles, 3 CTAs/SM ========================
#define SM_A     0          // 64 rows x 512B, chunk^row swizzled = 32768
#define SM_BBUF  32768      // 2 x 16384, SW128 layout
#define SM_PART  32768      // phase-0 overlay: 64 x 65 floats = 16640 (B dead then)
#define SM_RED   32768      // post-loop overlay: u64[64*16] = 8192
#define SM_REDF  40960      // post-loop overlay: float[64*16] = 4096
#define SM_AROW  65536      // 64 floats
#define SM_TOTAL 65792

extern __shared__ char smem[];

__global__ void __launch_bounds__(256, 3)
vq_kernel(const float* __restrict__ X, int npix)
{
    const int tid = threadIdx.x, lane = tid & 31, wid = tid >> 5;
    const int warp_m = wid & 1, warp_n = wid >> 1;
    const int p0 = blockIdx.x * 64;
    const u32 sb = smem_to_u32(smem);

    // ---- phase 0: X -> fp16 A smem (swizzled) + x^2 quad partials ----
    float* part = (float*)(smem + SM_PART);
    const float4* Xg4 = (const float4*)X;
    #pragma unroll 4
    for (int i = 0; i < 16; i++) {
        int q = i * 256 + tid, row = q >> 6, kq = q & 63;
        float4 v = make_float4(0.f, 0.f, 0.f, 0.f);
        if (p0 + row < npix) v = Xg4[(size_t)(p0 + row) * 64 + kq];
        __half h0 = __float2half(v.x), h1 = __float2half(v.y);
        __half h2 = __float2half(v.z), h3 = __float2half(v.w);
        u32 hx = (u32)__half_as_ushort(h0) | ((u32)__half_as_ushort(h1) << 16);
        u32 hy = (u32)__half_as_ushort(h2) | ((u32)__half_as_ushort(h3) << 16);
        u32 aoff = (u32)(row * 512 + ((((kq >> 1) ^ (row & 7))) << 4) + (kq & 1) * 8);
        *(uint2*)(smem + SM_A + aoff) = make_uint2(hx, hy);
        part[row * 65 + kq] = ((v.x * v.x + v.y * v.y) + v.z * v.z) + v.w * v.w;
    }
    __syncthreads();
    float* arow = (float*)(smem + SM_AROW);
    if (tid < 64) {
        float a = 0.f;
        #pragma unroll
        for (int kq = 0; kq < 64; kq++) a += part[tid * 65 + kq];
        arow[tid] = a;
    }
    __syncthreads();
    float a_r[2][2];
    #pragma unroll
    for (int g = 0; g < 2; g++)
        #pragma unroll
        for (int h = 0; h < 2; h++)
            a_r[g][h] = arow[warp_m * 32 + g * 16 + (lane >> 2) + h * 8];
    __syncthreads();

    // ---- async B double buffer (blob pre-swizzled -> identity copy) ----
    auto issue_copy = [&](int g, int buf) {
        #pragma unroll
        for (int j = 0; j < 4; j++) {
            int idx = j * 256 + tid;
            u32 dst = sb + SM_BBUF + (u32)(buf * 16384 + idx * 16);
            const char* src = (const char*)g_wblob + (size_t)g * 16384 + (size_t)idx * 16;
            CP_ASYNC16(dst, src);
        }
        CP_COMMIT();
    };
    issue_copy(0, 0);
    issue_copy(1, 1);

    float acc[2][4][4];
    #pragma unroll
    for (int g = 0; g < 2; g++)
        #pragma unroll
        for (int n = 0; n < 4; n++)
            #pragma unroll
            for (int j = 0; j < 4; j++) acc[g][n][j] = 0.f;
    u64   m1[2][2];
    float m2f[2][2];
    #pragma unroll
    for (int g = 0; g < 2; g++) {
        m1[g][0] = m1[g][1] = ~0ull;
        m2f[g][0] = m2f[g][1] = 3.4e38f;
    }

    u32 arb[2], arx[2];
    #pragma unroll
    for (int gi = 0; gi < 2; gi++) {
        int r = warp_m * 32 + gi * 16 + (lane & 15);
        arb[gi] = sb + SM_A + (u32)(r * 512);
        arx[gi] = (u32)(r & 7);
    }
    const u32 as16 = (u32)(lane >> 4);
    u32 brb[2], brx[2];
    #pragma unroll
    for (int n2 = 0; n2 < 2; n2++) {
        int sym = warp_n * 32 + n2 * 16 + (lane & 7) + (lane >> 4) * 8;
        brb[n2] = sb + SM_BBUF + (u32)(sym * 128);
        brx[n2] = (u32)(sym & 7);
    }
    const u32 bs0 = (u32)((lane >> 3) & 1);

    for (int g = 0; g < 32; g++) {
        const int tile = g >> 2, c = g & 3, buf = g & 1;
        if (g == 31) { CP_WAIT0(); } else { CP_WAIT1(); }
        __syncthreads();
        #pragma unroll
        for (int ks = 0; ks < 4; ks++) {
            u32 af[2][4], bfr[2][4];
            const u32 ch = (u32)(c * 8 + ks * 2) + as16;
            #pragma unroll
            for (int gi = 0; gi < 2; gi++)
                LDSM4(af[gi][0], af[gi][1], af[gi][2], af[gi][3],
                      arb[gi] + ((ch ^ arx[gi]) << 4));
            const u32 bseg = (u32)(ks * 2) + bs0;
            #pragma unroll
            for (int n2 = 0; n2 < 2; n2++)
                LDSM4(bfr[n2][0], bfr[n2][1], bfr[n2][2], bfr[n2][3],
                      brb[n2] + (u32)(buf * 16384) + ((bseg ^ brx[n2]) << 4));
            #pragma unroll
            for (int gi = 0; gi < 2; gi++)
                #pragma unroll
                for (int nf = 0; nf < 4; nf++)
                    MMA16816(acc[gi][nf][0], acc[gi][nf][1], acc[gi][nf][2], acc[gi][nf][3],
                             af[gi][0], af[gi][1], af[gi][2], af[gi][3],
                             bfr[nf >> 1][(nf & 1) * 2], bfr[nf >> 1][(nf & 1) * 2 + 1]);
        }
        if (c == 3) {
            // d = fl(fl(A+B) - 2*(acc/1024)) ; -2^-9 exact in fma.  Also store r = d - A.
            const int tbase = tile * 128 + warp_n * 32;
            #pragma unroll
            for (int nf = 0; nf < 4; nf++) {
                const int sym0 = tbase + nf * 8 + (lane & 3) * 2;
                const float w0 = g_wnorm[sym0];
                const float w1 = g_wnorm[sym0 + 1];
                #pragma unroll
                for (int gi = 0; gi < 2; gi++) {
                    #pragma unroll
                    for (int h = 0; h < 2; h++) {
                        const int row = warp_m * 32 + gi * 16 + (lane >> 2) + h * 8;
                        float d0 = __fmaf_rn(-0.001953125f, acc[gi][nf][h * 2],
                                             __fadd_rn(a_r[gi][h], w0));
                        float d1 = __fmaf_rn(-0.001953125f, acc[gi][nf][h * 2 + 1],
                                             __fadd_rn(a_r[gi][h], w1));
                        if (p0 + row < npix) {
                            __half2 rp = __floats2half2_rn(__fsub_rn(d0, a_r[gi][h]),
                                                           __fsub_rn(d1, a_r[gi][h]));
                            *(u32*)(g_dstore + (size_t)(p0 + row) * 1024 + sym0) =
                                *(u32*)&rp;
                        }
                        u64 k0 = ((u64)__float_as_uint(d0) << 32) | (u32)sym0;
                        u64 k1 = ((u64)__float_as_uint(d1) << 32) | (u32)(sym0 + 1);
                        // fminf drops the NaN from the ~0ull sentinel
                        if (k0 < m1[gi][h]) {
                            m2f[gi][h] = fminf(m2f[gi][h],
                                               __uint_as_float((u32)(m1[gi][h] >> 32)));
                            m1[gi][h] = k0;
                        } else m2f[gi][h] = fminf(m2f[gi][h], d0);
                        if (k1 < m1[gi][h]) {
                            m2f[gi][h] = fminf(m2f[gi][h],
                                               __uint_as_float((u32)(m1[gi][h] >> 32)));
                            m1[gi][h] = k1;
                        } else m2f[gi][h] = fminf(m2f[gi][h], d1);
                        acc[gi][nf][h * 2] = 0.f;
                        acc[gi][nf][h * 2 + 1] = 0.f;
                    }
                }
            }
        }
        __syncthreads();
        if (g + 2 < 32) issue_copy(g + 2, buf);
    }
    __syncthreads();   // B buffers dead; RED overlay becomes live

    // ---- top-2 merge + per-pixel certified margin ----
    u64*   red2 = (u64*)(smem + SM_RED);
    float* redf = (float*)(smem + SM_REDF);
    const int slot = warp_n * 4 + (lane & 3);
    #pragma unroll
    for (int gi = 0; gi < 2; gi++)
        #pragma unroll
        for (int h = 0; h < 2; h++) {
            int row = warp_m * 32 + gi * 16 + (lane >> 2) + h * 8;
            red2[row * 16 + slot] = m1[gi][h];
            redf[row * 16 + slot] = m2f[gi][h];
        }
    __syncthreads();
    if (tid < 64) {
        u64 b1 = ~0ull;
        float b2 = 3.4e38f;
        #pragma unroll
        for (int t = 0; t < 16; t++) {
            u64 k1 = red2[tid * 16 + t];
            float f2 = redf[tid * 16 + t];
            if (k1 < b1) {
                b2 = fminf(b2, __uint_as_float((u32)(b1 >> 32)));
                b1 = k1;
            } else {
                b2 = fminf(b2, __uint_as_float((u32)(k1 >> 32)));
            }
            b2 = fminf(b2, f2);
        }
        // |x| sum from fp16 A tile (bound input only; constant covers fp16 quant)
        float sab = 0.f;
        const u32 rx7 = (u32)(tid & 7);
        #pragma unroll 8
        for (u32 ch = 0; ch < 32; ch++) {
            uint4 v = *(const uint4*)(smem + SM_A + tid * 512 + ((ch ^ rx7) << 4));
            const u32 wd[4] = {v.x, v.y, v.z, v.w};
            #pragma unroll
            for (int t = 0; t < 4; t++) {
                float2 f = __half22float2(*(const __half2*)&wd[t]);
                sab += fabsf(f.x) + fabsf(f.y);
            }
        }
        if (p0 + tid < npix) {
            g_code[p0 + tid] = (int)(u32)b1;
            float d1 = __uint_as_float((u32)(b1 >> 32));
            float wmax = __uint_as_float(g_wmaxb);
            float marg = sab * wmax * 0.00398f + 1.0e-4f;
            if (!(b2 - d1 > marg)) {
                int fs = atomicAdd(&g_flagcnt, 1);
                g_flaglist[fs] = p0 + tid;
            }
        }
    }
}

// ================= candfix: exact rescore of CANDIDATES only ========================
__device__ __forceinline__ u64 chain_key(const float* xr, const float* __restrict__ W,
                                         int sym, float A) {
    const float4* wp = (const float4*)(W + (size_t)sym * 256);
    float acc = 0.f;
    #pragma unroll 8
    for (int k = 0; k < 64; k++) {
        float4 w4 = __ldg(&wp[k]);
        float4 x4 = *(const float4*)(xr + k * 4);
        acc = __fmaf_rn(x4.x, w4.x, acc);
        acc = __fmaf_rn(x4.y, w4.y, acc);
        acc = __fmaf_rn(x4.z, w4.z, acc);
        acc = __fmaf_rn(x4.w, w4.w, acc);
    }
    float d = __fmaf_rn(-2.f, acc, __fadd_rn(A, g_wnorm[sym]));
    return ((u64)__float_as_uint(d) << 32) | (u32)sym;
}

__global__ void __launch_bounds__(256, 1)
candfix_kernel(const float* __restrict__ X, const float* __restrict__ W)
{
    __shared__ float xrow[8][256];
    __shared__ float pp[8][64];
    __shared__ int   clist[8][34];
    __shared__ int   scnt[8];
    __shared__ float sA[8];
    const int lane = threadIdx.x & 31, w = threadIdx.x >> 5;
    const int wg = blockIdx.x * 8 + w, nw = gridDim.x * 8;
    const int cnt = g_flagcnt;
    const float wmax = __uint_as_float(g_wmaxb);

    for (int i = wg; i < cnt; i += nw) {
        const int pixel = g_flaglist[i];
        float sabs_l = 0.f;
        #pragma unroll
        for (int j = 0; j < 2; j++) {
            int kq = lane + j * 32;
            float4 v = ((const float4*)X)[(size_t)pixel * 64 + kq];
            *(float4*)&xrow[w][kq * 4] = v;
            pp[w][kq] = ((v.x * v.x + v.y * v.y) + v.z * v.z) + v.w * v.w;
            sabs_l += ((fabsf(v.x) + fabsf(v.y)) + fabsf(v.z)) + fabsf(v.w);
        }
        if (lane == 0) scnt[w] = 0;
        __syncwarp();
        if (lane == 0) {
            float a = 0.f;
            #pragma unroll
            for (int k = 0; k < 64; k++) a += pp[w][k];
            sA[w] = a;
        }
        #pragma unroll
        for (int o = 16; o; o >>= 1) sabs_l += __shfl_xor_sync(0xffffffffu, sabs_l, o);
        __syncwarp();
        const float A = sA[w];

        const uint4* rrow = (const uint4*)(g_dstore + (size_t)pixel * 1024);
        uint4 rv[4];
        float rmin = 3.4e38f;
        #pragma unroll
        for (int j = 0; j < 4; j++) {
            rv[j] = rrow[lane * 4 + j];
            const u32 wd[4] = {rv[j].x, rv[j].y, rv[j].z, rv[j].w};
            #pragma unroll
            for (int t = 0; t < 4; t++) {
                float2 f = __half22float2(*(const __half2*)&wd[t]);
                rmin = fminf(rmin, fminf(f.x, f.y));
            }
        }
        #pragma unroll
        for (int o = 16; o; o >>= 1)
            rmin = fminf(rmin, __shfl_xor_sync(0xffffffffu, rmin, o));
        const float thr = rmin + sabs_l * wmax * 0.004f + 6.5e-4f;

        #pragma unroll
        for (int j = 0; j < 4; j++) {
            const u32 wd[4] = {rv[j].x, rv[j].y, rv[j].z, rv[j].w};
            #pragma unroll
            for (int t = 0; t < 4; t++) {
                float2 f = __half22float2(*(const __half2*)&wd[t]);
                int sym = (lane * 16 + j * 4 + t) * 2;
                if (f.x <= thr) {
                    int pos = atomicAdd(&scnt[w], 1);
                    if (pos < 33) clist[w][pos] = sym;
                }
                if (f.y <= thr) {
                    int pos = atomicAdd(&scnt[w], 1);
                    if (pos < 33) clist[w][pos] = sym + 1;
                }
            }
        }
        __syncwarp();
        const int n = scnt[w];
        u64 key = ~0ull;
        if (n <= 32) {
            if (lane < n) key = chain_key(xrow[w], W, clist[w][lane], A);
        } else {
            for (int sym = lane; sym < 1024; sym += 32) {
                u64 k2 = chain_key(xrow[w], W, sym, A);
                if (k2 < key) key = k2;
            }
        }
        #pragma unroll
        for (int o = 16; o; o >>= 1) {
            u64 other = __shfl_xor_sync(0xffffffffu, key, o);
            if (other < key) key = other;
        }
        if (lane == 0) g_code[pixel] = (int)(u32)key;
        __syncwarp();
    }
}

// ================= gather + deviation + tail (last block), 64 px/CTA ================
__global__ void gather_kernel(const float* __restrict__ X, const float* __restrict__ W,
                              float* __restrict__ out, int npix, long long out_cap)
{
    __shared__ float psum[256];
    __shared__ int codes[64];
    __shared__ int lastflag;
    const int tid = threadIdx.x;
    const int p0 = blockIdx.x * 64;
    if (tid < 64) codes[tid] = (p0 + tid < npix) ? g_code[p0 + tid] : 0;
    __syncthreads();
    const float4* Xg4 = (const float4*)X;
    const float4* Wg4 = (const float4*)W;
    float4* out4 = (float4*)out;
    float dsum = 0.f;
    #pragma unroll 4
    for (int i = 0; i < 16; i++) {
        int q = i * 256 + tid, row = q >> 6, kq = q & 63;
        long long gp = p0 + row;
        if (gp < npix) {
            int c = codes[row];
            float4 wv = Wg4[(size_t)c * 64 + kq];
            float4 xv = Xg4[gp * 64 + kq];
            float t0 = wv.x - xv.x, t1 = wv.y - xv.y;
            float t2 = wv.z - xv.z, t3 = wv.w - xv.w;
            float4 ov;
            ov.x = xv.x + t0; ov.y = xv.y + t1; ov.z = xv.z + t2; ov.w = xv.w + t3;
            long long e = gp * 64 + kq;
            if (e * 4 + 3 < out_cap) out4[e] = ov;
            dsum += t0 * t0 + t1 * t1 + t2 * t2 + t3 * t3;
        }
    }
    psum[tid] = dsum;
    __syncthreads();
    #pragma unroll
    for (int sft = 128; sft > 0; sft >>= 1) {
        if (tid < sft) psum[tid] += psum[tid + sft];
        __syncthreads();
    }
    if (tid == 0) {
        atomicAdd(&g_devsum, (double)psum[0]);
        __threadfence();
        int done = atomicAdd(&g_blkdone, 1);
        lastflag = (done == (int)gridDim.x - 1);
    }
    __syncthreads();
    if (lastflag) {
        double dev = 1.25 * (*(volatile double*)&g_devsum) / (double)((long long)npix * 256);
        long long n = (long long)npix * 256;
        for (long long i = n + tid; i < out_cap; i += blockDim.x)
            out[i] = (float)dev;
    }
}

// ================= launch ===========================================================
extern "C" void kernel_launch(void* const* d_in, const int* in_sizes, int n_in,
                              void* d_out, int out_size) {
    const float* X = (const float*)d_in[0];
    const float* W = (const float*)d_in[1];
    float* out = (float*)d_out;
    const int npix = in_sizes[0] / 256;
    const int S = in_sizes[1] / 256;

    cudaFuncSetAttribute(vq_kernel, cudaFuncAttributeMaxDynamicSharedMemorySize, SM_TOTAL);

    prep_kernel<<<S, 256>>>(W);
    vq_kernel<<<(npix + 63) / 64, 256, SM_TOTAL>>>(X, npix);
    candfix_kernel<<<296, 256>>>(X, W);
    gather_kernel<<<(npix + 63) / 64, 256>>>(X, W, out, npix, (long long)out_size);
}

// round 15
// speedup vs baseline: 1.3081x; 1.0727x over previous
#include <cuda_runtime.h>
#include <cuda_fp16.h>
#include <cstdint>

typedef unsigned long long u64;
typedef uint32_t u32;

__device__ double g_devsum;
__device__ int    g_flagcnt;
__device__ int    g_blkdone;
__device__ u32    g_wmaxb;          // zero-init; monotone atomicMax -> replay-deterministic
__device__ float  g_wnorm[1024];
__device__ int    g_code[65536];
__device__ int    g_flaglist[65536];
// [tile8][chunk4] regions of 16KB: SW128-swizzled [sym128][k64] fp16 (w scaled by 1024)
__device__ __align__(16) unsigned char g_wblob[32 * 16384];
// approximate scores: r = d_app - A, fp16, [pixel][sym] (2KB per pixel)
__device__ __align__(16) unsigned short g_dstore[65536 * 1024];

__device__ __forceinline__ u32 smem_to_u32(const void* p) {
    u32 a;
    asm("{ .reg .u64 t; cvta.to.shared.u64 t, %1; cvt.u32.u64 %0, t; }" : "=r"(a) : "l"(p));
    return a;
}
#define SW128(o) ((o) ^ (((o) >> 3) & 0x70))

#define LDSM4(r0, r1, r2, r3, addr) \
    asm volatile("ldmatrix.sync.aligned.m8n8.x4.shared.b16 {%0,%1,%2,%3}, [%4];" \
                 : "=r"(r0), "=r"(r1), "=r"(r2), "=r"(r3) : "r"(addr))

#define MMA16816(c0, c1, c2, c3, a0, a1, a2, a3, b0, b1) \
    asm volatile("mma.sync.aligned.m16n8k16.row.col.f32.f16.f16.f32 " \
                 "{%0,%1,%2,%3},{%4,%5,%6,%7},{%8,%9},{%0,%1,%2,%3};" \
                 : "+f"(c0), "+f"(c1), "+f"(c2), "+f"(c3) \
                 : "r"(a0), "r"(a1), "r"(a2), "r"(a3), "r"(b0), "r"(b1))

#define CP_ASYNC16(dst, src) \
    asm volatile("cp.async.cg.shared.global [%0], [%1], 16;" :: "r"(dst), "l"(src))
#define CP_COMMIT() asm volatile("cp.async.commit_group;")
#define CP_WAIT1()  asm volatile("cp.async.wait_group 1;")
#define CP_WAIT0()  asm volatile("cp.async.wait_group 0;")

// ================= prep: wnorm + wmax + fp16 W blob (scaled 1024, SW128) ============
__global__ void prep_kernel(const float* __restrict__ W) {
    int s = blockIdx.x, tid = threadIdx.x;
    __shared__ float red[8], redm[8];
    float v = W[s * 256 + tid];
    float acc = v * v;
    float am = fabsf(v);
    #pragma unroll
    for (int o = 16; o; o >>= 1) {
        acc += __shfl_xor_sync(0xffffffffu, acc, o);
        am = fmaxf(am, __shfl_xor_sync(0xffffffffu, am, o));
    }
    if ((tid & 31) == 0) { red[tid >> 5] = acc; redm[tid >> 5] = am; }
    __syncthreads();
    if (tid == 0) {
        float t = 0.f, m = 0.f;
        #pragma unroll
        for (int i = 0; i < 8; i++) { t += red[i]; m = fmaxf(m, redm[i]); }
        g_wnorm[s] = t;
        atomicMax(&g_wmaxb, __float_as_uint(m));
        if (s == 0) { g_devsum = 0.0; g_flagcnt = 0; g_blkdone = 0; }
    }
    int tile = s >> 7, sym = s & 127, c = tid >> 6, k = tid & 63;
    __half h = __float2half(v * 1024.0f);
    u32 off = SW128((u32)(sym * 128 + k * 2));
    *(__half*)(g_wblob + (size_t)(tile * 4 + c) * 16384 + off) = h;
}

// ================= vq: fp16 HMMA GEMM, M=64 tiles, 3 CTAs/SM ========================
#define SM_A     0          // 64 rows x 512B, chunk^row swizzled = 32768
#define SM_BBUF  32768      // 2 x 16384, SW128 layout
#define SM_PART  32768      // phase-0 overlay: 64 x 65 floats = 16640 (B dead then)
#define SM_RED   32768      // post-loop overlay: u64[64*16] = 8192
#define SM_REDF  40960      // post-loop overlay: float[64*16] = 4096
#define SM_AROW  65536      // 64 floats
#define SM_TOTAL 65792

extern __shared__ char smem[];

__global__ void __launch_bounds__(256, 3)
vq_kernel(const float* __restrict__ X, int npix)
{
    const int tid = threadIdx.x, lane = tid & 31, wid = tid >> 5;
    const int warp_m = wid & 1, warp_n = wid >> 1;
    const int p0 = blockIdx.x * 64;
    const u32 sb = smem_to_u32(smem);

    // ---- phase 0: X -> fp16 A smem (swizzled) + x^2 quad partials ----
    float* part = (float*)(smem + SM_PART);
    const float4* Xg4 = (const float4*)X;
    #pragma unroll 4
    for (int i = 0; i < 16; i++) {
        int q = i * 256 + tid, row = q >> 6, kq = q & 63;
        float4 v = make_float4(0.f, 0.f, 0.f, 0.f);
        if (p0 + row < npix) v = Xg4[(size_t)(p0 + row) * 64 + kq];
        __half h0 = __float2half(v.x), h1 = __float2half(v.y);
        __half h2 = __float2half(v.z), h3 = __float2half(v.w);
        u32 hx = (u32)__half_as_ushort(h0) | ((u32)__half_as_ushort(h1) << 16);
        u32 hy = (u32)__half_as_ushort(h2) | ((u32)__half_as_ushort(h3) << 16);
        u32 aoff = (u32)(row * 512 + ((((kq >> 1) ^ (row & 7))) << 4) + (kq & 1) * 8);
        *(uint2*)(smem + SM_A + aoff) = make_uint2(hx, hy);
        part[row * 65 + kq] = ((v.x * v.x + v.y * v.y) + v.z * v.z) + v.w * v.w;
    }
    __syncthreads();
    float* arow = (float*)(smem + SM_AROW);
    if (tid < 64) {
        float a = 0.f;
        #pragma unroll
        for (int kq = 0; kq < 64; kq++) a += part[tid * 65 + kq];
        arow[tid] = a;
    }
    __syncthreads();
    float a_r[2][2];
    #pragma unroll
    for (int g = 0; g < 2; g++)
        #pragma unroll
        for (int h = 0; h < 2; h++)
            a_r[g][h] = arow[warp_m * 32 + g * 16 + (lane >> 2) + h * 8];
    __syncthreads();

    // ---- async B double buffer (blob pre-swizzled -> identity copy) ----
    auto issue_copy = [&](int g, int buf) {
        #pragma unroll
        for (int j = 0; j < 4; j++) {
            int idx = j * 256 + tid;
            u32 dst = sb + SM_BBUF + (u32)(buf * 16384 + idx * 16);
            const char* src = (const char*)g_wblob + (size_t)g * 16384 + (size_t)idx * 16;
            CP_ASYNC16(dst, src);
        }
        CP_COMMIT();
    };
    issue_copy(0, 0);
    issue_copy(1, 1);

    float acc[2][4][4];
    #pragma unroll
    for (int g = 0; g < 2; g++)
        #pragma unroll
        for (int n = 0; n < 4; n++)
            #pragma unroll
            for (int j = 0; j < 4; j++) acc[g][n][j] = 0.f;
    u64   m1[2][2];
    float m2f[2][2];
    #pragma unroll
    for (int g = 0; g < 2; g++) {
        m1[g][0] = m1[g][1] = ~0ull;
        m2f[g][0] = m2f[g][1] = 3.4e38f;
    }

    u32 arb[2], arx[2];
    #pragma unroll
    for (int gi = 0; gi < 2; gi++) {
        int r = warp_m * 32 + gi * 16 + (lane & 15);
        arb[gi] = sb + SM_A + (u32)(r * 512);
        arx[gi] = (u32)(r & 7);
    }
    const u32 as16 = (u32)(lane >> 4);
    u32 brb[2], brx[2];
    #pragma unroll
    for (int n2 = 0; n2 < 2; n2++) {
        int sym = warp_n * 32 + n2 * 16 + (lane & 7) + (lane >> 4) * 8;
        brb[n2] = sb + SM_BBUF + (u32)(sym * 128);
        brx[n2] = (u32)(sym & 7);
    }
    const u32 bs0 = (u32)((lane >> 3) & 1);

    for (int g = 0; g < 32; g++) {
        const int tile = g >> 2, c = g & 3, buf = g & 1;
        if (g == 31) { CP_WAIT0(); } else { CP_WAIT1(); }
        __syncthreads();
        #pragma unroll
        for (int ks = 0; ks < 4; ks++) {
            u32 af[2][4], bfr[2][4];
            const u32 ch = (u32)(c * 8 + ks * 2) + as16;
            #pragma unroll
            for (int gi = 0; gi < 2; gi++)
                LDSM4(af[gi][0], af[gi][1], af[gi][2], af[gi][3],
                      arb[gi] + ((ch ^ arx[gi]) << 4));
            const u32 bseg = (u32)(ks * 2) + bs0;
            #pragma unroll
            for (int n2 = 0; n2 < 2; n2++)
                LDSM4(bfr[n2][0], bfr[n2][1], bfr[n2][2], bfr[n2][3],
                      brb[n2] + (u32)(buf * 16384) + ((bseg ^ brx[n2]) << 4));
            #pragma unroll
            for (int gi = 0; gi < 2; gi++)
                #pragma unroll
                for (int nf = 0; nf < 4; nf++)
                    MMA16816(acc[gi][nf][0], acc[gi][nf][1], acc[gi][nf][2], acc[gi][nf][3],
                             af[gi][0], af[gi][1], af[gi][2], af[gi][3],
                             bfr[nf >> 1][(nf & 1) * 2], bfr[nf >> 1][(nf & 1) * 2 + 1]);
        }
        __syncthreads();                       // all reads of buf done CTA-wide
        if (g + 2 < 32) issue_copy(g + 2, buf); // overlap copy with epilogue below
        if (c == 3) {
            // d = fl(fl(A+B) - 2*(acc/1024)) ; -2^-9 exact in fma.  Also store r = d - A.
            const int tbase = tile * 128 + warp_n * 32;
            #pragma unroll
            for (int nf = 0; nf < 4; nf++) {
                const int sym0 = tbase + nf * 8 + (lane & 3) * 2;
                const float w0 = g_wnorm[sym0];
                const float w1 = g_wnorm[sym0 + 1];
                #pragma unroll
                for (int gi = 0; gi < 2; gi++) {
                    #pragma unroll
                    for (int h = 0; h < 2; h++) {
                        const int row = warp_m * 32 + gi * 16 + (lane >> 2) + h * 8;
                        float d0 = __fmaf_rn(-0.001953125f, acc[gi][nf][h * 2],
                                             __fadd_rn(a_r[gi][h], w0));
                        float d1 = __fmaf_rn(-0.001953125f, acc[gi][nf][h * 2 + 1],
                                             __fadd_rn(a_r[gi][h], w1));
                        if (p0 + row < npix) {
                            __half2 rp = __floats2half2_rn(__fsub_rn(d0, a_r[gi][h]),
                                                           __fsub_rn(d1, a_r[gi][h]));
                            __stcs((u32*)(g_dstore + (size_t)(p0 + row) * 1024 + sym0),
                                   *(u32*)&rp);
                        }
                        u64 k0 = ((u64)__float_as_uint(d0) << 32) | (u32)sym0;
                        u64 k1 = ((u64)__float_as_uint(d1) << 32) | (u32)(sym0 + 1);
                        // fminf drops the NaN from the ~0ull sentinel
                        if (k0 < m1[gi][h]) {
                            m2f[gi][h] = fminf(m2f[gi][h],
                                               __uint_as_float((u32)(m1[gi][h] >> 32)));
                            m1[gi][h] = k0;
                        } else m2f[gi][h] = fminf(m2f[gi][h], d0);
                        if (k1 < m1[gi][h]) {
                            m2f[gi][h] = fminf(m2f[gi][h],
                                               __uint_as_float((u32)(m1[gi][h] >> 32)));
                            m1[gi][h] = k1;
                        } else m2f[gi][h] = fminf(m2f[gi][h], d1);
                        acc[gi][nf][h * 2] = 0.f;
                        acc[gi][nf][h * 2 + 1] = 0.f;
                    }
                }
            }
        }
    }
    __syncthreads();   // B buffers dead; RED overlay becomes live

    // ---- top-2 merge + per-pixel certified margin ----
    u64*   red2 = (u64*)(smem + SM_RED);
    float* redf = (float*)(smem + SM_REDF);
    const int slot = warp_n * 4 + (lane & 3);
    #pragma unroll
    for (int gi = 0; gi < 2; gi++)
        #pragma unroll
        for (int h = 0; h < 2; h++) {
            int row = warp_m * 32 + gi * 16 + (lane >> 2) + h * 8;
            red2[row * 16 + slot] = m1[gi][h];
            redf[row * 16 + slot] = m2f[gi][h];
        }
    __syncthreads();
    if (tid < 64) {
        u64 b1 = ~0ull;
        float b2 = 3.4e38f;
        #pragma unroll
        for (int t = 0; t < 16; t++) {
            u64 k1 = red2[tid * 16 + t];
            float f2 = redf[tid * 16 + t];
            if (k1 < b1) {
                b2 = fminf(b2, __uint_as_float((u32)(b1 >> 32)));
                b1 = k1;
            } else {
                b2 = fminf(b2, __uint_as_float((u32)(k1 >> 32)));
            }
            b2 = fminf(b2, f2);
        }
        // |x| sum from fp16 A tile (bound input only; constant covers fp16 quant)
        float sab = 0.f;
        const u32 rx7 = (u32)(tid & 7);
        #pragma unroll 8
        for (u32 ch = 0; ch < 32; ch++) {
            uint4 v = *(const uint4*)(smem + SM_A + tid * 512 + ((ch ^ rx7) << 4));
            const u32 wd[4] = {v.x, v.y, v.z, v.w};
            #pragma unroll
            for (int t = 0; t < 4; t++) {
                float2 f = __half22float2(*(const __half2*)&wd[t]);
                sab += fabsf(f.x) + fabsf(f.y);
            }
        }
        if (p0 + tid < npix) {
            g_code[p0 + tid] = (int)(u32)b1;
            float d1 = __uint_as_float((u32)(b1 >> 32));
            float wmax = __uint_as_float(g_wmaxb);
            // marg >= 2e + ulp with e <= sab*wmax*2^-10 (fp16 quant of x and w)
            float marg = sab * wmax * 0.0025f + 1.0e-4f;
            if (!(b2 - d1 > marg)) {
                int fs = atomicAdd(&g_flagcnt, 1);
                g_flaglist[fs] = p0 + tid;
            }
        }
    }
}

// ================= candfix: exact rescore of CANDIDATES only ========================
__device__ __forceinline__ u64 chain_key(const float* xr, const float* __restrict__ W,
                                         int sym, float A) {
    const float4* wp = (const float4*)(W + (size_t)sym * 256);
    float acc = 0.f;
    #pragma unroll 8
    for (int k = 0; k < 64; k++) {
        float4 w4 = __ldg(&wp[k]);
        float4 x4 = *(const float4*)(xr + k * 4);
        acc = __fmaf_rn(x4.x, w4.x, acc);
        acc = __fmaf_rn(x4.y, w4.y, acc);
        acc = __fmaf_rn(x4.z, w4.z, acc);
        acc = __fmaf_rn(x4.w, w4.w, acc);
    }
    float d = __fmaf_rn(-2.f, acc, __fadd_rn(A, g_wnorm[sym]));
    return ((u64)__float_as_uint(d) << 32) | (u32)sym;
}

__global__ void __launch_bounds__(256, 1)
candfix_kernel(const float* __restrict__ X, const float* __restrict__ W)
{
    __shared__ float xrow[8][256];
    __shared__ float pp[8][64];
    __shared__ int   clist[8][34];
    __shared__ int   scnt[8];
    __shared__ float sA[8];
    const int lane = threadIdx.x & 31, w = threadIdx.x >> 5;
    const int wg = blockIdx.x * 8 + w, nw = gridDim.x * 8;
    const int cnt = g_flagcnt;
    const float wmax = __uint_as_float(g_wmaxb);

    for (int i = wg; i < cnt; i += nw) {
        const int pixel = g_flaglist[i];
        float sabs_l = 0.f;
        #pragma unroll
        for (int j = 0; j < 2; j++) {
            int kq = lane + j * 32;
            float4 v = ((const float4*)X)[(size_t)pixel * 64 + kq];
            *(float4*)&xrow[w][kq * 4] = v;
            pp[w][kq] = ((v.x * v.x + v.y * v.y) + v.z * v.z) + v.w * v.w;
            sabs_l += ((fabsf(v.x) + fabsf(v.y)) + fabsf(v.z)) + fabsf(v.w);
        }
        if (lane == 0) scnt[w] = 0;
        __syncwarp();
        if (lane == 0) {
            float a = 0.f;
            #pragma unroll
            for (int k = 0; k < 64; k++) a += pp[w][k];
            sA[w] = a;
        }
        #pragma unroll
        for (int o = 16; o; o >>= 1) sabs_l += __shfl_xor_sync(0xffffffffu, sabs_l, o);
        __syncwarp();
        const float A = sA[w];

        const uint4* rrow = (const uint4*)(g_dstore + (size_t)pixel * 1024);
        uint4 rv[4];
        float rmin = 3.4e38f;
        #pragma unroll
        for (int j = 0; j < 4; j++) {
            rv[j] = __ldcs(&rrow[lane * 4 + j]);
            const u32 wd[4] = {rv[j].x, rv[j].y, rv[j].z, rv[j].w};
            #pragma unroll
            for (int t = 0; t < 4; t++) {
                float2 f = __half22float2(*(const __half2*)&wd[t]);
                rmin = fminf(rmin, fminf(f.x, f.y));
            }
        }
        #pragma unroll
        for (int o = 16; o; o >>= 1)
            rmin = fminf(rmin, __shfl_xor_sync(0xffffffffu, rmin, o));
        const float thr = rmin + sabs_l * wmax * 0.004f + 6.5e-4f;

        #pragma unroll
        for (int j = 0; j < 4; j++) {
            const u32 wd[4] = {rv[j].x, rv[j].y, rv[j].z, rv[j].w};
            #pragma unroll
            for (int t = 0; t < 4; t++) {
                float2 f = __half22float2(*(const __half2*)&wd[t]);
                int sym = (lane * 16 + j * 4 + t) * 2;
                if (f.x <= thr) {
                    int pos = atomicAdd(&scnt[w], 1);
                    if (pos < 33) clist[w][pos] = sym;
                }
                if (f.y <= thr) {
                    int pos = atomicAdd(&scnt[w], 1);
                    if (pos < 33) clist[w][pos] = sym + 1;
                }
            }
        }
        __syncwarp();
        const int n = scnt[w];
        u64 key = ~0ull;
        if (n <= 32) {
            if (lane < n) key = chain_key(xrow[w], W, clist[w][lane], A);
        } else {
            for (int sym = lane; sym < 1024; sym += 32) {
                u64 k2 = chain_key(xrow[w], W, sym, A);
                if (k2 < key) key = k2;
            }
        }
        #pragma unroll
        for (int o = 16; o; o >>= 1) {
            u64 other = __shfl_xor_sync(0xffffffffu, key, o);
            if (other < key) key = other;
        }
        if (lane == 0) g_code[pixel] = (int)(u32)key;
        __syncwarp();
    }
}

// ================= gather + deviation + tail (last block), 64 px/CTA ================
__global__ void gather_kernel(const float* __restrict__ X, const float* __restrict__ W,
                              float* __restrict__ out, int npix, long long out_cap)
{
    __shared__ float psum[256];
    __shared__ int codes[64];
    __shared__ int lastflag;
    const int tid = threadIdx.x;
    const int p0 = blockIdx.x * 64;
    if (tid < 64) codes[tid] = (p0 + tid < npix) ? g_code[p0 + tid] : 0;
    __syncthreads();
    const float4* Xg4 = (const float4*)X;
    const float4* Wg4 = (const float4*)W;
    float4* out4 = (float4*)out;
    float dsum = 0.f;
    #pragma unroll 4
    for (int i = 0; i < 16; i++) {
        int q = i * 256 + tid, row = q >> 6, kq = q & 63;
        long long gp = p0 + row;
        if (gp < npix) {
            int c = codes[row];
            float4 wv = Wg4[(size_t)c * 64 + kq];
            float4 xv = __ldcs(&Xg4[gp * 64 + kq]);
            float t0 = wv.x - xv.x, t1 = wv.y - xv.y;
            float t2 = wv.z - xv.z, t3 = wv.w - xv.w;
            float4 ov;
            ov.x = xv.x + t0; ov.y = xv.y + t1; ov.z = xv.z + t2; ov.w = xv.w + t3;
            long long e = gp * 64 + kq;
            if (e * 4 + 3 < out_cap) __stcs(&out4[e], ov);
            dsum += t0 * t0 + t1 * t1 + t2 * t2 + t3 * t3;
        }
    }
    psum[tid] = dsum;
    __syncthreads();
    #pragma unroll
    for (int sft = 128; sft > 0; sft >>= 1) {
        if (tid < sft) psum[tid] += psum[tid + sft];
        __syncthreads();
    }
    if (tid == 0) {
        atomicAdd(&g_devsum, (double)psum[0]);
        __threadfence();
        int done = atomicAdd(&g_blkdone, 1);
        lastflag = (done == (int)gridDim.x - 1);
    }
    __syncthreads();
    if (lastflag) {
        double dev = 1.25 * (*(volatile double*)&g_devsum) / (double)((long long)npix * 256);
        long long n = (long long)npix * 256;
        for (long long i = n + tid; i < out_cap; i += blockDim.x)
            out[i] = (float)dev;
    }
}

// ================= launch ===========================================================
extern "C" void kernel_launch(void* const* d_in, const int* in_sizes, int n_in,
                              void* d_out, int out_size) {
    const float* X = (const float*)d_in[0];
    const float* W = (const float*)d_in[1];
    float* out = (float*)d_out;
    const int npix = in_sizes[0] / 256;
    const int S = in_sizes[1] / 256;

    cudaFuncSetAttribute(vq_kernel, cudaFuncAttributeMaxDynamicSharedMemorySize, SM_TOTAL);

    prep_kernel<<<S, 256>>>(W);
    vq_kernel<<<(npix + 63) / 64, 256, SM_TOTAL>>>(X, npix);
    candfix_kernel<<<296, 256>>>(X, W);
    gather_kernel<<<(npix + 63) / 64, 256>>>(X, W, out, npix, (long long)out_size);
}